// round 15
// baseline (speedup 1.0000x reference)
#include <cuda_runtime.h>
#include <cuda.h>
#include <cuda_fp16.h>
#include <math.h>
#include <stdint.h>

// ---------------- problem constants ----------------
#define BATCH 4
#define SEQ   2048
#define NTOK  (BATCH * SEQ)        // 8192
#define DIM   1024
#define HID   4096
#define NEXP  8
#define TOPK  2
#define NPAIR (NTOK * TOPK)        // 16384
#define PADMAX 17408               // 16384 + 8*128 pad slack

// GEMM tiling (fp16, 4-stage pipeline, static smem < 48KB)
#define BM 128
#define BN 128
#define BK 16
#define NSTG 4
#define AK 24                      // A smem row stride (halfs)
#define BNP 136                    // B smem row stride (halfs)
#define NSLAB1 (NEXP * (HID / BN)) // 256 W1 slabs (expert x n-tile)

// ---------------- device scratch ----------------
__device__ __align__(1024) __half g_x16[(size_t)PADMAX * DIM];
__device__ __align__(1024) __half g_h16[(size_t)PADMAX * HID];
__device__ __align__(1024) float  g_y  [(size_t)PADMAX * DIM];
__device__ __align__(1024) __half g_w1h[(size_t)NEXP * DIM * HID];
__device__ __align__(1024) __half g_w2h[(size_t)NEXP * HID * DIM];
__device__ int   g_w1flag[NSLAB1];
__device__ int   g_count[NEXP];
__device__ int   g_fill[NEXP];
__device__ int   g_poffset[NEXP];
__device__ int   g_tilecum[NEXP + 1];
__device__ int   g_top_i[NPAIR];
__device__ float g_top_v[NPAIR];
__device__ float g_wt[PADMAX];
__device__ int   g_slot[NPAIR];

// ---------------- helpers ----------------
__device__ __forceinline__ uint32_t smem_u32(const void* p) {
    uint32_t a;
    asm("{ .reg .u64 t; cvta.to.shared.u64 t, %1; cvt.u32.u64 %0, t; }" : "=r"(a) : "l"(p));
    return a;
}
__device__ __forceinline__ void cp_async16(uint32_t sdst, const void* gsrc) {
    asm volatile("cp.async.cg.shared.global [%0], [%1], 16;"
                 :: "r"(sdst), "l"(gsrc) : "memory");
}
__device__ __forceinline__ void cp_commit() {
    asm volatile("cp.async.commit_group;" ::: "memory");
}
__device__ __forceinline__ void cp_wait0() {
    asm volatile("cp.async.wait_group 0;" ::: "memory");
}
__device__ __forceinline__ void cp_wait1() {
    asm volatile("cp.async.wait_group 1;" ::: "memory");
}
__device__ __forceinline__ void cp_wait2() {
    asm volatile("cp.async.wait_group 2;" ::: "memory");
}
__device__ __forceinline__ void ldsm_x4(uint32_t* r, uint32_t addr) {
    asm volatile("ldmatrix.sync.aligned.m8n8.x4.shared.b16 {%0,%1,%2,%3}, [%4];"
                 : "=r"(r[0]), "=r"(r[1]), "=r"(r[2]), "=r"(r[3]) : "r"(addr));
}
__device__ __forceinline__ void ldsm_x4_t(uint32_t* r, uint32_t addr) {
    asm volatile("ldmatrix.sync.aligned.m8n8.x4.trans.shared.b16 {%0,%1,%2,%3}, [%4];"
                 : "=r"(r[0]), "=r"(r[1]), "=r"(r[2]), "=r"(r[3]) : "r"(addr));
}
__device__ __forceinline__ void mma_f16(float* d, const uint32_t* a,
                                        uint32_t b0, uint32_t b1) {
    asm volatile(
        "mma.sync.aligned.m16n8k16.row.col.f32.f16.f16.f32 "
        "{%0,%1,%2,%3}, {%4,%5,%6,%7}, {%8,%9}, {%0,%1,%2,%3};"
        : "+f"(d[0]), "+f"(d[1]), "+f"(d[2]), "+f"(d[3])
        : "r"(a[0]), "r"(a[1]), "r"(a[2]), "r"(a[3]), "r"(b0), "r"(b1));
}

// ---------------- routing kernels ----------------
__global__ void init_kernel() {
    int i = blockIdx.x * blockDim.x + threadIdx.x;
    if (i < NEXP) { g_count[i] = 0; g_fill[i] = 0; }
    if (i < NSLAB1) g_w1flag[i] = 0;
}

__global__ void gating_kernel(const float* __restrict__ x,
                              const float* __restrict__ Wg,
                              const float* __restrict__ bg) {
    int warp = (blockIdx.x * blockDim.x + threadIdx.x) >> 5;
    int lane = threadIdx.x & 31;
    if (warp >= NTOK) return;
    const float* xr = x + (size_t)warp * DIM;
    float acc[NEXP];
#pragma unroll
    for (int e = 0; e < NEXP; e++) acc[e] = 0.f;
    for (int d = lane; d < DIM; d += 32) {
        float xv = xr[d];
        const float* wr = Wg + d * NEXP;
#pragma unroll
        for (int e = 0; e < NEXP; e++) acc[e] += xv * wr[e];
    }
#pragma unroll
    for (int off = 16; off > 0; off >>= 1)
#pragma unroll
        for (int e = 0; e < NEXP; e++)
            acc[e] += __shfl_xor_sync(0xFFFFFFFFu, acc[e], off);
    if (lane == 0) {
        float logit[NEXP];
#pragma unroll
        for (int e = 0; e < NEXP; e++) logit[e] = acc[e] + bg[e];
        float mx = logit[0];
#pragma unroll
        for (int e = 1; e < NEXP; e++) mx = fmaxf(mx, logit[e]);
        float p[NEXP], s = 0.f;
#pragma unroll
        for (int e = 0; e < NEXP; e++) { p[e] = expf(logit[e] - mx); s += p[e]; }
        int i0 = 0; float v0 = p[0];
#pragma unroll
        for (int e = 1; e < NEXP; e++) if (p[e] > v0) { v0 = p[e]; i0 = e; }
        int i1 = -1; float v1 = -1.f;
#pragma unroll
        for (int e = 0; e < NEXP; e++)
            if (e != i0 && p[e] > v1) { v1 = p[e]; i1 = e; }
        float inv = 1.f / s;
        g_top_i[2 * warp + 0] = i0;  g_top_v[2 * warp + 0] = v0 * inv;
        g_top_i[2 * warp + 1] = i1;  g_top_v[2 * warp + 1] = v1 * inv;
        atomicAdd(&g_count[i0], 1);
        atomicAdd(&g_count[i1], 1);
    }
}

__global__ void scan_kernel() {
    if (threadIdx.x == 0) {
        int off = 0, tc = 0;
        for (int e = 0; e < NEXP; e++) {
            g_poffset[e] = off;
            g_tilecum[e] = tc;
            int t = (g_count[e] + BM - 1) / BM;
            tc += t;
            off += t * BM;
        }
        g_tilecum[NEXP] = tc;
    }
}

__global__ void scatter_kernel() {
    int t = blockIdx.x * blockDim.x + threadIdx.x;
    if (t >= NTOK) return;
#pragma unroll
    for (int k = 0; k < TOPK; k++) {
        int e = g_top_i[2 * t + k];
        int pos = atomicAdd(&g_fill[e], 1);
        int s = g_poffset[e] + pos;
        g_wt[s] = g_top_v[2 * t + k];
        g_slot[2 * t + k] = s;
    }
}

// gather x rows into padded slots as fp16 (rne)
__global__ void gather_kernel(const float* __restrict__ x) {
    int pair = blockIdx.x;
    int t = pair >> 1;
    int slot = g_slot[pair];
    const float4* src = (const float4*)(x + (size_t)t * DIM);
    uint2* dst = (uint2*)(g_x16 + (size_t)slot * DIM);
    for (int i = threadIdx.x; i < DIM / 4; i += blockDim.x) {
        float4 v = src[i];
        __half2 h01 = __floats2half2_rn(v.x, v.y);
        __half2 h23 = __floats2half2_rn(v.z, v.w);
        uint2 u;
        u.x = *(uint32_t*)&h01; u.y = *(uint32_t*)&h23;
        dst[i] = u;
    }
}

// ---------------- grouped GEMM: fp16 mma m16n8k16, 4-stage cp.async --------
// C tile 128x128, 256 threads, 8 warps (2m x 4n), warp tile 64x32, BK=16.
// STAGE1: before the mainloop, claim-convert-spin its W1 slab (e, n-tile)
// fp32->fp16 (first CTA converts, others spin on the flag). After the tile,
// convert a grid-stride chunk of W2 (R14 scheme). GEMM2 launches after GEMM1
// completes, so all conversions are globally done by then.
template <int KDIM, int NTOT, bool STAGE1>
__global__ void __launch_bounds__(256, 2) moe_gemm_kernel(
        const float* __restrict__ bias,
        const float4* __restrict__ w1src,
        const float4* __restrict__ w2src) {
    __shared__ __half sA[NSTG][BM][AK];
    __shared__ __half sB[NSTG][BK][BNP];
    __shared__ int s_claim;

    int mt = blockIdx.y;
    int tid = threadIdx.x;

    if (mt < g_tilecum[NEXP]) {
        int e = 0;
#pragma unroll
        for (int i = 0; i < NEXP - 1; i++)
            if (mt >= g_tilecum[i + 1]) e = i + 1;
        int rowbase = g_poffset[e] + (mt - g_tilecum[e]) * BM;
        int n0 = blockIdx.x * BN;

        // ---- STAGE1: ensure W1 slab (e, blockIdx.x) is converted ----
        if (STAGE1) {
            int slab = e * (NTOT / BN) + blockIdx.x;
            if (tid == 0) s_claim = atomicCAS(&g_w1flag[slab], 0, 1);
            __syncthreads();
            if (s_claim == 0) {
                // winner: convert 1024 rows x 128 cols (32 float4/row)
                uint2* dst = (uint2*)(g_w1h + (size_t)e * KDIM * NTOT + n0);
                const float4* src = w1src + ((size_t)e * KDIM * NTOT + n0) / 4;
                const int row_f4 = NTOT / 4;        // float4 per full row
                for (int idx = tid; idx < KDIM * (BN / 4); idx += 256) {
                    int k = idx >> 5;               // BN/4 = 32 chunks per row
                    int cc = idx & 31;
                    float4 v = src[(size_t)k * row_f4 + cc];
                    __half2 h01 = __floats2half2_rn(v.x, v.y);
                    __half2 h23 = __floats2half2_rn(v.z, v.w);
                    uint2 u;
                    u.x = *(uint32_t*)&h01; u.y = *(uint32_t*)&h23;
                    // dst row stride NTOT halfs = NTOT/4 uint2
                    dst[(size_t)k * (NTOT / 4) + cc] = u;
                }
                __syncthreads();
                __threadfence();
                if (tid == 0) atomicExch(&g_w1flag[slab], 2);
            } else if (s_claim == 1) {
                if (tid == 0) {
                    while (atomicAdd(&g_w1flag[slab], 0) != 2) {}
                }
                __syncthreads();
                __threadfence();
            }
            // s_claim == 2: already converted, proceed
        }

        const __half* Abuf = STAGE1 ? g_x16 : g_h16;
        const __half* Wbuf = STAGE1 ? g_w1h : g_w2h;

        const __half* Ag = Abuf + (size_t)rowbase * KDIM;
        const __half* Bg = Wbuf + (size_t)e * KDIM * NTOT + n0;

        int wid = tid >> 5, lane = tid & 31;
        int wm = wid >> 2, wn = wid & 3;        // 2x4 warp grid
        int c = lane & 3, r = lane >> 2;
        int t8 = lane & 7, q = lane >> 3;

        int a_lrow = (q & 1) * 8 + t8;
        int a_lcol = (q >> 1) * 8;
        int b_lrow = (q & 1) * 8 + t8;
        int b_lcol = (q >> 1) * 8;

        int a_row = tid >> 1, a_cj = (tid & 1) * 8;   // 128 rows x 2 chunks
        int b_row = tid >> 4, b_cj = (tid & 15) * 8;  // 16 rows x 16 chunks

        float acc[4][4][4];
#pragma unroll
        for (int i = 0; i < 4; i++)
#pragma unroll
            for (int j = 0; j < 4; j++)
#pragma unroll
                for (int p = 0; p < 4; p++) acc[i][j][p] = 0.f;

        constexpr int NIT = KDIM / BK;

        auto load_stage = [&](int it) {
            int s = it & (NSTG - 1);
            int k0 = it * BK;
            cp_async16(smem_u32(&sA[s][a_row][a_cj]),
                       Ag + (size_t)a_row * KDIM + k0 + a_cj);
            cp_async16(smem_u32(&sB[s][b_row][b_cj]),
                       Bg + (size_t)(k0 + b_row) * NTOT + b_cj);
            cp_commit();
        };

        load_stage(0);
        load_stage(1);
        load_stage(2);

#pragma unroll 1
        for (int it = 0; it < NIT; ++it) {
            int rem = NIT - 1 - it;
            if (rem >= 2)      cp_wait2();
            else if (rem == 1) cp_wait1();
            else               cp_wait0();
            __syncthreads();

            if (it + 3 < NIT) load_stage(it + 3);

            int s = it & (NSTG - 1);
            uint32_t a[4][4];
#pragma unroll
            for (int mf = 0; mf < 4; mf++) {
                int m = wm * 64 + mf * 16;
                ldsm_x4(a[mf], smem_u32(&sA[s][m + a_lrow][a_lcol]));
            }
#pragma unroll
            for (int np = 0; np < 2; np++) {
                uint32_t b[4];
                int nb = wn * 32 + np * 16;
                ldsm_x4_t(b, smem_u32(&sB[s][b_lrow][nb + b_lcol]));
#pragma unroll
                for (int mf = 0; mf < 4; mf++) {
                    mma_f16(acc[mf][np * 2 + 0], a[mf], b[0], b[1]);
                    mma_f16(acc[mf][np * 2 + 1], a[mf], b[2], b[3]);
                }
            }
        }

        // ---- epilogue ----
        const float* brow = bias + (size_t)e * NTOT;
#pragma unroll
        for (int mf = 0; mf < 4; mf++) {
            int m = wm * 64 + mf * 16 + r;
            int grow0 = rowbase + m;
            int grow1 = grow0 + 8;
            float wt0 = 0.f, wt1 = 0.f;
            if (!STAGE1) { wt0 = g_wt[grow0]; wt1 = g_wt[grow1]; }
#pragma unroll
            for (int nf = 0; nf < 4; nf++) {
                int gcol = n0 + wn * 32 + nf * 8 + 2 * c;
                float bb0 = brow[gcol], bb1 = brow[gcol + 1];
                float v00 = acc[mf][nf][0] + bb0;
                float v01 = acc[mf][nf][1] + bb1;
                float v10 = acc[mf][nf][2] + bb0;
                float v11 = acc[mf][nf][3] + bb1;
                if (STAGE1) {
                    __half2 h0 = __floats2half2_rn(fmaxf(v00, 0.f), fmaxf(v01, 0.f));
                    __half2 h1 = __floats2half2_rn(fmaxf(v10, 0.f), fmaxf(v11, 0.f));
                    *(uint32_t*)(g_h16 + (size_t)grow0 * NTOT + gcol) = *(uint32_t*)&h0;
                    *(uint32_t*)(g_h16 + (size_t)grow1 * NTOT + gcol) = *(uint32_t*)&h1;
                } else {
                    float2 o0, o1;
                    o0.x = v00 * wt0; o0.y = v01 * wt0;
                    o1.x = v10 * wt1; o1.y = v11 * wt1;
                    *(float2*)(g_y + (size_t)grow0 * NTOT + gcol) = o0;
                    *(float2*)(g_y + (size_t)grow1 * NTOT + gcol) = o1;
                }
            }
        }
    }

    // ---- STAGE1 only: convert this CTA's grid-stride chunk of W2 ----
    if (STAGE1) {
        const int n4 = NEXP * HID * DIM / 4;
        uint2* o2 = (uint2*)g_w2h;
        int cta = blockIdx.y * gridDim.x + blockIdx.x;
        int nctas = gridDim.x * gridDim.y;
        int stride = nctas * 256;
        for (int i = cta * 256 + tid; i < n4; i += stride) {
            float4 v = w2src[i];
            __half2 h01 = __floats2half2_rn(v.x, v.y);
            __half2 h23 = __floats2half2_rn(v.z, v.w);
            uint2 u;
            u.x = *(uint32_t*)&h01; u.y = *(uint32_t*)&h23;
            o2[i] = u;
        }
    }
}

// ---------------- combine ----------------
__global__ void combine_kernel(float* __restrict__ out) {
    int t = blockIdx.x;
    int s0 = g_slot[2 * t + 0];
    int s1 = g_slot[2 * t + 1];
    const float4* y0 = (const float4*)(g_y + (size_t)s0 * DIM);
    const float4* y1 = (const float4*)(g_y + (size_t)s1 * DIM);
    float4* o = (float4*)(out + (size_t)t * DIM);
    for (int i = threadIdx.x; i < DIM / 4; i += blockDim.x) {
        float4 a = y0[i], b = y1[i];
        float4 rr;
        rr.x = a.x + b.x; rr.y = a.y + b.y; rr.z = a.z + b.z; rr.w = a.w + b.w;
        o[i] = rr;
    }
}

// ---------------- host launch ----------------
extern "C" void kernel_launch(void* const* d_in, const int* in_sizes, int n_in,
                              void* d_out, int out_size) {
    const float* x  = (const float*)d_in[0];
    const float* Wg = (const float*)d_in[1];
    const float* bg = (const float*)d_in[2];
    const float* W1 = (const float*)d_in[3];
    const float* b1 = (const float*)d_in[4];
    const float* W2 = (const float*)d_in[5];
    const float* b2 = (const float*)d_in[6];
    float* out = (float*)d_out;

    init_kernel<<<1, 256>>>();
    gating_kernel<<<(NTOK * 32) / 256, 256>>>(x, Wg, bg);
    scan_kernel<<<1, 32>>>();
    scatter_kernel<<<(NTOK + 255) / 256, 256>>>();
    gather_kernel<<<NPAIR, 128>>>(x);

    int mtiles = NPAIR / BM + NEXP;  // 136 worst case
    moe_gemm_kernel<DIM, HID, true><<<dim3(HID / BN, mtiles), 256>>>(
        b1, (const float4*)W1, (const float4*)W2);
    moe_gemm_kernel<HID, DIM, false><<<dim3(DIM / BN, mtiles), 256>>>(
        b2, (const float4*)W1, (const float4*)W2);

    combine_kernel<<<NTOK, 256>>>(out);
}

// round 16
// speedup vs baseline: 1.0579x; 1.0579x over previous
#include <cuda_runtime.h>
#include <cuda.h>
#include <cuda_fp16.h>
#include <math.h>
#include <stdint.h>

// ---------------- problem constants ----------------
#define BATCH 4
#define SEQ   2048
#define NTOK  (BATCH * SEQ)        // 8192
#define DIM   1024
#define HID   4096
#define NEXP  8
#define TOPK  2
#define NPAIR (NTOK * TOPK)        // 16384
#define PADMAX 17408               // 16384 + 8*128 pad slack

// GEMM tiling (fp16, 4-stage pipeline, static smem < 48KB)
#define BM 128
#define BN 128
#define BK 16
#define NSTG 4
#define AK 24                      // A smem row stride (halfs)
#define BNP 136                    // B smem row stride (halfs)

// ---------------- device scratch ----------------
__device__ __align__(1024) __half g_x16[(size_t)PADMAX * DIM];
__device__ __align__(1024) __half g_h16[(size_t)PADMAX * HID];
__device__ __align__(1024) float  g_y  [(size_t)PADMAX * DIM];
__device__ __align__(1024) __half g_w1h[(size_t)NEXP * DIM * HID];
__device__ __align__(1024) __half g_w2h[(size_t)NEXP * HID * DIM];
__device__ int   g_count[NEXP];
__device__ int   g_fill[NEXP];
__device__ int   g_poffset[NEXP];
__device__ int   g_tilecum[NEXP + 1];
__device__ int   g_top_i[NPAIR];
__device__ float g_top_v[NPAIR];
__device__ float g_wt[PADMAX];
__device__ int   g_slot[NPAIR];

// ---------------- helpers ----------------
__device__ __forceinline__ uint32_t smem_u32(const void* p) {
    uint32_t a;
    asm("{ .reg .u64 t; cvta.to.shared.u64 t, %1; cvt.u32.u64 %0, t; }" : "=r"(a) : "l"(p));
    return a;
}
__device__ __forceinline__ void cp_async16(uint32_t sdst, const void* gsrc) {
    asm volatile("cp.async.cg.shared.global [%0], [%1], 16;"
                 :: "r"(sdst), "l"(gsrc) : "memory");
}
__device__ __forceinline__ void cp_commit() {
    asm volatile("cp.async.commit_group;" ::: "memory");
}
__device__ __forceinline__ void cp_wait0() {
    asm volatile("cp.async.wait_group 0;" ::: "memory");
}
__device__ __forceinline__ void cp_wait1() {
    asm volatile("cp.async.wait_group 1;" ::: "memory");
}
__device__ __forceinline__ void cp_wait2() {
    asm volatile("cp.async.wait_group 2;" ::: "memory");
}
__device__ __forceinline__ void ldsm_x4(uint32_t* r, uint32_t addr) {
    asm volatile("ldmatrix.sync.aligned.m8n8.x4.shared.b16 {%0,%1,%2,%3}, [%4];"
                 : "=r"(r[0]), "=r"(r[1]), "=r"(r[2]), "=r"(r[3]) : "r"(addr));
}
__device__ __forceinline__ void ldsm_x4_t(uint32_t* r, uint32_t addr) {
    asm volatile("ldmatrix.sync.aligned.m8n8.x4.trans.shared.b16 {%0,%1,%2,%3}, [%4];"
                 : "=r"(r[0]), "=r"(r[1]), "=r"(r[2]), "=r"(r[3]) : "r"(addr));
}
__device__ __forceinline__ void mma_f16(float* d, const uint32_t* a,
                                        uint32_t b0, uint32_t b1) {
    asm volatile(
        "mma.sync.aligned.m16n8k16.row.col.f32.f16.f16.f32 "
        "{%0,%1,%2,%3}, {%4,%5,%6,%7}, {%8,%9}, {%0,%1,%2,%3};"
        : "+f"(d[0]), "+f"(d[1]), "+f"(d[2]), "+f"(d[3])
        : "r"(a[0]), "r"(a[1]), "r"(a[2]), "r"(a[3]), "r"(b0), "r"(b1));
}

// ---------------- routing kernels ----------------
__global__ void init_kernel() {
    int i = threadIdx.x;
    if (i < NEXP) { g_count[i] = 0; g_fill[i] = 0; }
}

// gating + grid-stride W1 fp32->fp16 conversion tail (no sync needed:
// gating kernel completes before GEMM1 launches on the same stream)
__global__ void gating_kernel(const float* __restrict__ x,
                              const float* __restrict__ Wg,
                              const float* __restrict__ bg,
                              const float4* __restrict__ w1src) {
    int warp = (blockIdx.x * blockDim.x + threadIdx.x) >> 5;
    int lane = threadIdx.x & 31;
    if (warp < NTOK) {
        const float* xr = x + (size_t)warp * DIM;
        float acc[NEXP];
#pragma unroll
        for (int e = 0; e < NEXP; e++) acc[e] = 0.f;
        for (int d = lane; d < DIM; d += 32) {
            float xv = xr[d];
            const float* wr = Wg + d * NEXP;
#pragma unroll
            for (int e = 0; e < NEXP; e++) acc[e] += xv * wr[e];
        }
#pragma unroll
        for (int off = 16; off > 0; off >>= 1)
#pragma unroll
            for (int e = 0; e < NEXP; e++)
                acc[e] += __shfl_xor_sync(0xFFFFFFFFu, acc[e], off);
        if (lane == 0) {
            float logit[NEXP];
#pragma unroll
            for (int e = 0; e < NEXP; e++) logit[e] = acc[e] + bg[e];
            float mx = logit[0];
#pragma unroll
            for (int e = 1; e < NEXP; e++) mx = fmaxf(mx, logit[e]);
            float p[NEXP], s = 0.f;
#pragma unroll
            for (int e = 0; e < NEXP; e++) { p[e] = expf(logit[e] - mx); s += p[e]; }
            int i0 = 0; float v0 = p[0];
#pragma unroll
            for (int e = 1; e < NEXP; e++) if (p[e] > v0) { v0 = p[e]; i0 = e; }
            int i1 = -1; float v1 = -1.f;
#pragma unroll
            for (int e = 0; e < NEXP; e++)
                if (e != i0 && p[e] > v1) { v1 = p[e]; i1 = e; }
            float inv = 1.f / s;
            g_top_i[2 * warp + 0] = i0;  g_top_v[2 * warp + 0] = v0 * inv;
            g_top_i[2 * warp + 1] = i1;  g_top_v[2 * warp + 1] = v1 * inv;
            atomicAdd(&g_count[i0], 1);
            atomicAdd(&g_count[i1], 1);
        }
    }

    // ---- conversion tail: W1 fp32 -> fp16 (rne), grid-stride ----
    {
        const int n4 = NEXP * DIM * HID / 4;
        uint2* o1 = (uint2*)g_w1h;
        int i = blockIdx.x * blockDim.x + threadIdx.x;
        int stride = gridDim.x * blockDim.x;
        for (; i < n4; i += stride) {
            float4 v = w1src[i];
            __half2 h01 = __floats2half2_rn(v.x, v.y);
            __half2 h23 = __floats2half2_rn(v.z, v.w);
            uint2 u;
            u.x = *(uint32_t*)&h01; u.y = *(uint32_t*)&h23;
            o1[i] = u;
        }
    }
}

__global__ void scan_kernel() {
    if (threadIdx.x == 0) {
        int off = 0, tc = 0;
        for (int e = 0; e < NEXP; e++) {
            g_poffset[e] = off;
            g_tilecum[e] = tc;
            int t = (g_count[e] + BM - 1) / BM;
            tc += t;
            off += t * BM;
        }
        g_tilecum[NEXP] = tc;
    }
}

__global__ void scatter_kernel() {
    int t = blockIdx.x * blockDim.x + threadIdx.x;
    if (t >= NTOK) return;
#pragma unroll
    for (int k = 0; k < TOPK; k++) {
        int e = g_top_i[2 * t + k];
        int pos = atomicAdd(&g_fill[e], 1);
        int s = g_poffset[e] + pos;
        g_wt[s] = g_top_v[2 * t + k];
        g_slot[2 * t + k] = s;
    }
}

// gather x rows into padded slots as fp16 (rne)
__global__ void gather_kernel(const float* __restrict__ x) {
    int pair = blockIdx.x;
    int t = pair >> 1;
    int slot = g_slot[pair];
    const float4* src = (const float4*)(x + (size_t)t * DIM);
    uint2* dst = (uint2*)(g_x16 + (size_t)slot * DIM);
    for (int i = threadIdx.x; i < DIM / 4; i += blockDim.x) {
        float4 v = src[i];
        __half2 h01 = __floats2half2_rn(v.x, v.y);
        __half2 h23 = __floats2half2_rn(v.z, v.w);
        uint2 u;
        u.x = *(uint32_t*)&h01; u.y = *(uint32_t*)&h23;
        dst[i] = u;
    }
}

// ---------------- grouped GEMM: fp16 mma m16n8k16, 4-stage cp.async --------
// C tile 128x128, 256 threads, 8 warps (2m x 4n), warp tile 64x32, BK=16.
// STAGE1 additionally converts its grid-stride chunk of W2 fp32->fp16 after
// the tile epilogue (overlapped with other CTAs' MMA work; GEMM2 launches
// only after this kernel completes, so conversion is globally done).
template <int KDIM, int NTOT, bool STAGE1>
__global__ void __launch_bounds__(256, 2) moe_gemm_kernel(
        const float* __restrict__ bias,
        const float4* __restrict__ w2src) {
    __shared__ __half sA[NSTG][BM][AK];
    __shared__ __half sB[NSTG][BK][BNP];

    int mt = blockIdx.y;
    int tid = threadIdx.x;

    if (mt < g_tilecum[NEXP]) {
        int e = 0;
#pragma unroll
        for (int i = 0; i < NEXP - 1; i++)
            if (mt >= g_tilecum[i + 1]) e = i + 1;
        int rowbase = g_poffset[e] + (mt - g_tilecum[e]) * BM;
        int n0 = blockIdx.x * BN;

        const __half* Abuf = STAGE1 ? g_x16 : g_h16;
        const __half* Wbuf = STAGE1 ? g_w1h : g_w2h;

        const __half* Ag = Abuf + (size_t)rowbase * KDIM;
        const __half* Bg = Wbuf + (size_t)e * KDIM * NTOT + n0;

        int wid = tid >> 5, lane = tid & 31;
        int wm = wid >> 2, wn = wid & 3;        // 2x4 warp grid
        int c = lane & 3, r = lane >> 2;
        int t8 = lane & 7, q = lane >> 3;

        int a_lrow = (q & 1) * 8 + t8;
        int a_lcol = (q >> 1) * 8;
        int b_lrow = (q & 1) * 8 + t8;
        int b_lcol = (q >> 1) * 8;

        int a_row = tid >> 1, a_cj = (tid & 1) * 8;   // 128 rows x 2 chunks
        int b_row = tid >> 4, b_cj = (tid & 15) * 8;  // 16 rows x 16 chunks

        float acc[4][4][4];
#pragma unroll
        for (int i = 0; i < 4; i++)
#pragma unroll
            for (int j = 0; j < 4; j++)
#pragma unroll
                for (int p = 0; p < 4; p++) acc[i][j][p] = 0.f;

        constexpr int NIT = KDIM / BK;

        auto load_stage = [&](int it) {
            int s = it & (NSTG - 1);
            int k0 = it * BK;
            cp_async16(smem_u32(&sA[s][a_row][a_cj]),
                       Ag + (size_t)a_row * KDIM + k0 + a_cj);
            cp_async16(smem_u32(&sB[s][b_row][b_cj]),
                       Bg + (size_t)(k0 + b_row) * NTOT + b_cj);
            cp_commit();
        };

        load_stage(0);
        load_stage(1);
        load_stage(2);

#pragma unroll 1
        for (int it = 0; it < NIT; ++it) {
            int rem = NIT - 1 - it;
            if (rem >= 2)      cp_wait2();
            else if (rem == 1) cp_wait1();
            else               cp_wait0();
            __syncthreads();

            if (it + 3 < NIT) load_stage(it + 3);

            int s = it & (NSTG - 1);
            uint32_t a[4][4];
#pragma unroll
            for (int mf = 0; mf < 4; mf++) {
                int m = wm * 64 + mf * 16;
                ldsm_x4(a[mf], smem_u32(&sA[s][m + a_lrow][a_lcol]));
            }
#pragma unroll
            for (int np = 0; np < 2; np++) {
                uint32_t b[4];
                int nb = wn * 32 + np * 16;
                ldsm_x4_t(b, smem_u32(&sB[s][b_lrow][nb + b_lcol]));
#pragma unroll
                for (int mf = 0; mf < 4; mf++) {
                    mma_f16(acc[mf][np * 2 + 0], a[mf], b[0], b[1]);
                    mma_f16(acc[mf][np * 2 + 1], a[mf], b[2], b[3]);
                }
            }
        }

        // ---- epilogue ----
        const float* brow = bias + (size_t)e * NTOT;
#pragma unroll
        for (int mf = 0; mf < 4; mf++) {
            int m = wm * 64 + mf * 16 + r;
            int grow0 = rowbase + m;
            int grow1 = grow0 + 8;
            float wt0 = 0.f, wt1 = 0.f;
            if (!STAGE1) { wt0 = g_wt[grow0]; wt1 = g_wt[grow1]; }
#pragma unroll
            for (int nf = 0; nf < 4; nf++) {
                int gcol = n0 + wn * 32 + nf * 8 + 2 * c;
                float bb0 = brow[gcol], bb1 = brow[gcol + 1];
                float v00 = acc[mf][nf][0] + bb0;
                float v01 = acc[mf][nf][1] + bb1;
                float v10 = acc[mf][nf][2] + bb0;
                float v11 = acc[mf][nf][3] + bb1;
                if (STAGE1) {
                    __half2 h0 = __floats2half2_rn(fmaxf(v00, 0.f), fmaxf(v01, 0.f));
                    __half2 h1 = __floats2half2_rn(fmaxf(v10, 0.f), fmaxf(v11, 0.f));
                    *(uint32_t*)(g_h16 + (size_t)grow0 * NTOT + gcol) = *(uint32_t*)&h0;
                    *(uint32_t*)(g_h16 + (size_t)grow1 * NTOT + gcol) = *(uint32_t*)&h1;
                } else {
                    float2 o0, o1;
                    o0.x = v00 * wt0; o0.y = v01 * wt0;
                    o1.x = v10 * wt1; o1.y = v11 * wt1;
                    *(float2*)(g_y + (size_t)grow0 * NTOT + gcol) = o0;
                    *(float2*)(g_y + (size_t)grow1 * NTOT + gcol) = o1;
                }
            }
        }
    }

    // ---- STAGE1 only: convert this CTA's grid-stride chunk of W2 ----
    if (STAGE1) {
        const int n4 = NEXP * HID * DIM / 4;
        uint2* o2 = (uint2*)g_w2h;
        int cta = blockIdx.y * gridDim.x + blockIdx.x;
        int nctas = gridDim.x * gridDim.y;
        int stride = nctas * 256;
        for (int i = cta * 256 + tid; i < n4; i += stride) {
            float4 v = w2src[i];
            __half2 h01 = __floats2half2_rn(v.x, v.y);
            __half2 h23 = __floats2half2_rn(v.z, v.w);
            uint2 u;
            u.x = *(uint32_t*)&h01; u.y = *(uint32_t*)&h23;
            o2[i] = u;
        }
    }
}

// ---------------- combine ----------------
__global__ void combine_kernel(float* __restrict__ out) {
    int t = blockIdx.x;
    int s0 = g_slot[2 * t + 0];
    int s1 = g_slot[2 * t + 1];
    const float4* y0 = (const float4*)(g_y + (size_t)s0 * DIM);
    const float4* y1 = (const float4*)(g_y + (size_t)s1 * DIM);
    float4* o = (float4*)(out + (size_t)t * DIM);
    for (int i = threadIdx.x; i < DIM / 4; i += blockDim.x) {
        float4 a = y0[i], b = y1[i];
        float4 rr;
        rr.x = a.x + b.x; rr.y = a.y + b.y; rr.z = a.z + b.z; rr.w = a.w + b.w;
        o[i] = rr;
    }
}

// ---------------- host launch ----------------
extern "C" void kernel_launch(void* const* d_in, const int* in_sizes, int n_in,
                              void* d_out, int out_size) {
    const float* x  = (const float*)d_in[0];
    const float* Wg = (const float*)d_in[1];
    const float* bg = (const float*)d_in[2];
    const float* W1 = (const float*)d_in[3];
    const float* b1 = (const float*)d_in[4];
    const float* W2 = (const float*)d_in[5];
    const float* b2 = (const float*)d_in[6];
    float* out = (float*)d_out;

    init_kernel<<<1, 32>>>();
    gating_kernel<<<(NTOK * 32) / 256, 256>>>(x, Wg, bg, (const float4*)W1);
    scan_kernel<<<1, 32>>>();
    scatter_kernel<<<(NTOK + 255) / 256, 256>>>();
    gather_kernel<<<NPAIR, 128>>>(x);

    int mtiles = NPAIR / BM + NEXP;  // 136 worst case
    moe_gemm_kernel<DIM, HID, true><<<dim3(HID / BN, mtiles), 256>>>(
        b1, (const float4*)W2);
    moe_gemm_kernel<HID, DIM, false><<<dim3(DIM / BN, mtiles), 256>>>(
        b2, (const float4*)W2);

    combine_kernel<<<NTOK, 256>>>(out);
}